// round 5
// baseline (speedup 1.0000x reference)
#include <cuda_runtime.h>
#include <cstdint>

// ---------------- Problem constants ----------------
constexpr int NN = 16384;   // nodes per level
constexpr int DD = 256;     // feature dim
constexpr int KP = 16;      // in-degree
constexpr int LL = 16;      // levels

// ---------------- GEMM tiling ----------------
constexpr int BM = 64, BN = 128, BK = 32;
constexpr int PAD = 36;                    // SMEM row stride in floats (bank-conflict-free)
constexpr int A_FLOATS = BM * PAD;         // 2304 floats per buffer
constexpr int B_FLOATS = BN * PAD;         // 4608 floats per buffer
constexpr int SMEM_BYTES = 2 * (A_FLOATS + B_FLOATS) * 4;  // 55296

// ---------------- Scratch (__device__ globals; alloc-free rule) ----------------
__device__ float g_msg[NN * DD];
__device__ float g_W1t[DD * DD];   // W1^T : Wt[n][k] = W[k][n]
__device__ float g_W2t[DD * DD];

// ---------------- tf32 helpers (portable sm_80+ PTX; no 'a'-features) ----------------
__device__ __forceinline__ uint32_t f2tf(float f) {
    uint32_t r; asm("cvt.rna.tf32.f32 %0, %1;" : "=r"(r) : "f"(f)); return r;
}
__device__ __forceinline__ void mma_tf32(float* c, const uint32_t* a, const uint32_t* b) {
    asm volatile("mma.sync.aligned.m16n8k8.row.col.f32.tf32.tf32.f32 "
                 "{%0,%1,%2,%3}, {%4,%5,%6,%7}, {%8,%9}, {%0,%1,%2,%3};"
                 : "+f"(c[0]), "+f"(c[1]), "+f"(c[2]), "+f"(c[3])
                 : "r"(a[0]), "r"(a[1]), "r"(a[2]), "r"(a[3]), "r"(b[0]), "r"(b[1]));
}

// ---------------- Fused GEMM ----------------
// MODE 0: C = relu(A @ Bt^T + bias)                      (A is activations [NN,DD])
// MODE 1: C = relu(mean_p(A[idx[i,p]]) @ Bt^T + bias) + res   (gather-mean fused into A load)
// Bt is the weight pre-transposed to [n][k] (col-major B for mma row.col).
// Block: 256 threads = 8 warps (2 m x 4 n), warp tile 32x64... -> warp tile 32(m) x 32(n),
// per-warp frags: 2 m-frags (m16) x 4 n-frags (n8), k-chunks of 32 (4 k8 steps), 8 chunks.
template<int MODE, bool ADD_RES>
__global__ __launch_bounds__(256, 2) void gemm_mma(
    const float* __restrict__ A, const int* __restrict__ idx,
    const float* __restrict__ Bt, const float* __restrict__ bias,
    const float* __restrict__ res, float* __restrict__ C)
{
    extern __shared__ float sm[];
    uint32_t* Asu = (uint32_t*)sm;                    // [2][BM][PAD] tf32 bits
    uint32_t* Bsu = (uint32_t*)(sm + 2 * A_FLOATS);   // [2][BN][PAD]

    const int tid = threadIdx.x;
    const int lane = tid & 31, wid = tid >> 5;
    const int g = lane >> 2, t = lane & 3;
    const int wm = (wid & 1) * 32, wn = (wid >> 1) * 32;
    const int bm = blockIdx.y * BM, bn = blockIdx.x * BN;

    const float4* A4 = (const float4*)A;
    const float4* B4 = (const float4*)Bt;

    // MODE1: parent indices for this thread's gather row (4 threads share a row)
    int pr[KP];
    const int grow = tid >> 2;          // 0..63 : row within A tile
    const int gcs = (tid & 3) * 2;      // float4 index pair within 8-float4 chunk row
    if (MODE == 1) {
        const int4* ip = (const int4*)(idx + (size_t)(bm + grow) * KP);
        #pragma unroll
        for (int i = 0; i < 4; i++) {
            int4 v = ip[i];
            pr[i*4+0] = v.x; pr[i*4+1] = v.y; pr[i*4+2] = v.z; pr[i*4+3] = v.w;
        }
    }

    float4 pa[2];          // MODE0 A prefetch
    float4 s0, s1;         // MODE1 gather accumulators
    float4 pb[4];          // B prefetch

    auto prefetchA = [&](int kc) {
        if (MODE == 0) {
            #pragma unroll
            for (int i = 0; i < 2; i++) {
                int e = tid + i * 256, row = e >> 3, v = e & 7;
                pa[i] = A4[(size_t)(bm + row) * 64 + kc * 8 + v];
            }
        } else {
            s0 = make_float4(0.f, 0.f, 0.f, 0.f); s1 = s0;
            #pragma unroll
            for (int p = 0; p < KP; p++) {
                const float4* rp = A4 + (size_t)pr[p] * 64 + kc * 8 + gcs;
                float4 v0 = rp[0], v1 = rp[1];
                s0.x += v0.x; s0.y += v0.y; s0.z += v0.z; s0.w += v0.w;
                s1.x += v1.x; s1.y += v1.y; s1.z += v1.z; s1.w += v1.w;
            }
        }
    };
    auto prefetchB = [&](int kc) {
        #pragma unroll
        for (int i = 0; i < 4; i++) {
            int e = tid + i * 256, n = e >> 3, v = e & 7;
            pb[i] = B4[(size_t)(bn + n) * 64 + kc * 8 + v];
        }
    };
    auto stsAB = [&](int buf) {
        if (MODE == 0) {
            #pragma unroll
            for (int i = 0; i < 2; i++) {
                int e = tid + i * 256, row = e >> 3, v = e & 7;
                uint4 u = {f2tf(pa[i].x), f2tf(pa[i].y), f2tf(pa[i].z), f2tf(pa[i].w)};
                *(uint4*)(Asu + buf * A_FLOATS + row * PAD + v * 4) = u;
            }
        } else {
            const float inv = 1.0f / 16.0f;
            uint4 u0 = {f2tf(s0.x*inv), f2tf(s0.y*inv), f2tf(s0.z*inv), f2tf(s0.w*inv)};
            uint4 u1 = {f2tf(s1.x*inv), f2tf(s1.y*inv), f2tf(s1.z*inv), f2tf(s1.w*inv)};
            uint32_t* p = Asu + buf * A_FLOATS + grow * PAD + gcs * 4;
            *(uint4*)p = u0;
            *(uint4*)(p + 4) = u1;
        }
        #pragma unroll
        for (int i = 0; i < 4; i++) {
            int e = tid + i * 256, n = e >> 3, v = e & 7;
            uint4 u = {f2tf(pb[i].x), f2tf(pb[i].y), f2tf(pb[i].z), f2tf(pb[i].w)};
            *(uint4*)(Bsu + buf * B_FLOATS + n * PAD + v * 4) = u;
        }
    };

    float acc[2][4][4] = {};

    auto compute = [&](int buf) {
        const uint32_t* Ab = Asu + buf * A_FLOATS;
        const uint32_t* Bb = Bsu + buf * B_FLOATS;
        #pragma unroll
        for (int ks = 0; ks < 4; ks++) {
            const int k0 = ks * 8;
            uint32_t a[2][4], b[4][2];
            #pragma unroll
            for (int mf = 0; mf < 2; mf++) {
                const uint32_t* r0 = Ab + (wm + mf*16 + g) * PAD + k0 + t;
                const uint32_t* r1 = Ab + (wm + mf*16 + 8 + g) * PAD + k0 + t;
                a[mf][0] = r0[0]; a[mf][1] = r1[0]; a[mf][2] = r0[4]; a[mf][3] = r1[4];
            }
            #pragma unroll
            for (int nf = 0; nf < 4; nf++) {
                const uint32_t* rb = Bb + (wn + nf*8 + g) * PAD + k0 + t;
                b[nf][0] = rb[0]; b[nf][1] = rb[4];
            }
            #pragma unroll
            for (int mf = 0; mf < 2; mf++)
                #pragma unroll
                for (int nf = 0; nf < 4; nf++)
                    mma_tf32(acc[mf][nf], a[mf], b[nf]);
        }
    };

    // Software pipeline: reg-prefetch next chunk while computing current.
    prefetchA(0); prefetchB(0);
    stsAB(0);
    __syncthreads();
    #pragma unroll
    for (int kc = 0; kc < DD / BK; kc++) {
        if (kc < DD / BK - 1) { prefetchA(kc + 1); prefetchB(kc + 1); }
        compute(kc & 1);
        if (kc < DD / BK - 1) { stsAB((kc + 1) & 1); __syncthreads(); }
    }

    // Epilogue: bias + relu (+ residual)
    #pragma unroll
    for (int mf = 0; mf < 2; mf++) {
        const int r0 = bm + wm + mf*16 + g;
        #pragma unroll
        for (int nf = 0; nf < 4; nf++) {
            const int col = bn + wn + nf*8 + 2*t;
            float2 bb = *(const float2*)(bias + col);
            float2 v0, v1;
            v0.x = fmaxf(acc[mf][nf][0] + bb.x, 0.f);
            v0.y = fmaxf(acc[mf][nf][1] + bb.y, 0.f);
            v1.x = fmaxf(acc[mf][nf][2] + bb.x, 0.f);
            v1.y = fmaxf(acc[mf][nf][3] + bb.y, 0.f);
            if (ADD_RES) {
                float2 q0 = *(const float2*)(res + (size_t)r0 * DD + col);
                float2 q1 = *(const float2*)(res + (size_t)(r0 + 8) * DD + col);
                v0.x += q0.x; v0.y += q0.y; v1.x += q1.x; v1.y += q1.y;
            }
            *(float2*)(C + (size_t)r0 * DD + col) = v0;
            *(float2*)(C + (size_t)(r0 + 8) * DD + col) = v1;
        }
    }
}

// ---------------- 256x256 transpose (weights -> N-major B operand) ----------------
__global__ void transpose256(const float* __restrict__ W, float* __restrict__ Wt) {
    __shared__ float tbuf[32][33];
    const int bx = (blockIdx.x & 7) * 32;
    const int by = (blockIdx.x >> 3) * 32;
    const int x = threadIdx.x, y = threadIdx.y;
    #pragma unroll
    for (int i = 0; i < 32; i += 8)
        tbuf[y + i][x] = W[(by + y + i) * DD + bx + x];
    __syncthreads();
    #pragma unroll
    for (int i = 0; i < 32; i += 8)
        Wt[(bx + y + i) * DD + by + x] = tbuf[x][y + i];
}

// ---------------- Launch ----------------
extern "C" void kernel_launch(void* const* d_in, const int* in_sizes, int n_in,
                              void* d_out, int out_size)
{
    const float* x   = (const float*)d_in[0];   // [L, N, D]
    const int*   idx = (const int*)  d_in[1];   // [L-1, N, K]
    const float* W1  = (const float*)d_in[2];   // [D, D]
    const float* b1  = (const float*)d_in[3];   // [D]
    const float* W2  = (const float*)d_in[4];   // [D, D]
    const float* b2  = (const float*)d_in[5];   // [D]
    float* out = (float*)d_out;                 // [L, N, D]

    float *msgp, *w1t, *w2t;
    cudaGetSymbolAddress((void**)&msgp, g_msg);
    cudaGetSymbolAddress((void**)&w1t,  g_W1t);
    cudaGetSymbolAddress((void**)&w2t,  g_W2t);

    cudaFuncSetAttribute(gemm_mma<0, false>, cudaFuncAttributeMaxDynamicSharedMemorySize, SMEM_BYTES);
    cudaFuncSetAttribute(gemm_mma<1, true>,  cudaFuncAttributeMaxDynamicSharedMemorySize, SMEM_BYTES);

    const size_t lvl = (size_t)NN * DD;

    // Pre-transpose weights (B operand is col-major [n][k] for mma row.col)
    transpose256<<<64, dim3(32, 8)>>>(W1, w1t);
    transpose256<<<64, dim3(32, 8)>>>(W2, w2t);

    // Level 0: passthrough
    cudaMemcpyAsync(out, x, lvl * sizeof(float), cudaMemcpyDeviceToDevice);

    const dim3 grid(DD / BN, NN / BM);   // (2, 256)

    for (int l = 1; l < LL; l++) {
        const float* yprev = out + (size_t)(l - 1) * lvl;
        // msg = relu(yprev @ W1 + b1)
        gemm_mma<0, false><<<grid, 256, SMEM_BYTES>>>(yprev, nullptr, w1t, b1, nullptr, msgp);
        // y = relu(mean_p msg[idx] @ W2 + b2) + x[l]   (gather fused into A-load)
        gemm_mma<1, true><<<grid, 256, SMEM_BYTES>>>(msgp, idx + (size_t)(l - 1) * NN * KP,
                                                     w2t, b2, x + (size_t)l * lvl,
                                                     out + (size_t)l * lvl);
    }
}

// round 6
// speedup vs baseline: 1.0014x; 1.0014x over previous
#include <cuda_runtime.h>
#include <cstdint>

// ---------------- Problem constants ----------------
constexpr int NN = 16384;   // nodes per level
constexpr int DD = 256;     // feature dim
constexpr int KP = 16;      // in-degree
constexpr int LL = 16;      // levels

// ---------------- GEMM tiling ----------------
constexpr int BM = 64, BN = 128, BK = 32;
constexpr int PAD = 36;                    // SMEM row stride in floats (bank-conflict-free)
constexpr int A_FLOATS = BM * PAD;         // 2304 floats per buffer
constexpr int B_FLOATS = BN * PAD;         // 4608 floats per buffer
constexpr int SMEM_BYTES = 2 * (A_FLOATS + B_FLOATS) * 4;  // 55296

// ---------------- Scratch (__device__ globals; alloc-free rule) ----------------
__device__ float g_msg[NN * DD];
__device__ float g_W1t[DD * DD];   // W1^T : Wt[n][k] = W[k][n]
__device__ float g_W2t[DD * DD];

// ---------------- tf32 helpers (portable sm_80+ PTX; no 'a'-features) ----------------
__device__ __forceinline__ uint32_t f2tf(float f) {
    uint32_t r; asm("cvt.rna.tf32.f32 %0, %1;" : "=r"(r) : "f"(f)); return r;
}
__device__ __forceinline__ void mma_tf32(float* c, const uint32_t* a, const uint32_t* b) {
    asm volatile("mma.sync.aligned.m16n8k8.row.col.f32.tf32.tf32.f32 "
                 "{%0,%1,%2,%3}, {%4,%5,%6,%7}, {%8,%9}, {%0,%1,%2,%3};"
                 : "+f"(c[0]), "+f"(c[1]), "+f"(c[2]), "+f"(c[3])
                 : "r"(a[0]), "r"(a[1]), "r"(a[2]), "r"(a[3]), "r"(b[0]), "r"(b[1]));
}

// ---------------- Fused GEMM ----------------
// MODE 0: C = relu(A @ Bt^T + bias)                      (A is activations [NN,DD])
// MODE 1: C = relu(mean_p(A[idx[i,p]]) @ Bt^T + bias) + res   (gather-mean fused into A load)
// Bt is the weight pre-transposed to [n][k] (col-major B for mma row.col).
// Block: 256 threads = 8 warps (2 m x 4 n), warp tile 32x64... -> warp tile 32(m) x 32(n),
// per-warp frags: 2 m-frags (m16) x 4 n-frags (n8), k-chunks of 32 (4 k8 steps), 8 chunks.
template<int MODE, bool ADD_RES>
__global__ __launch_bounds__(256, 2) void gemm_mma(
    const float* __restrict__ A, const int* __restrict__ idx,
    const float* __restrict__ Bt, const float* __restrict__ bias,
    const float* __restrict__ res, float* __restrict__ C)
{
    extern __shared__ float sm[];
    uint32_t* Asu = (uint32_t*)sm;                    // [2][BM][PAD] tf32 bits
    uint32_t* Bsu = (uint32_t*)(sm + 2 * A_FLOATS);   // [2][BN][PAD]

    const int tid = threadIdx.x;
    const int lane = tid & 31, wid = tid >> 5;
    const int g = lane >> 2, t = lane & 3;
    const int wm = (wid & 1) * 32, wn = (wid >> 1) * 32;
    const int bm = blockIdx.y * BM, bn = blockIdx.x * BN;

    const float4* A4 = (const float4*)A;
    const float4* B4 = (const float4*)Bt;

    // MODE1: parent indices for this thread's gather row (4 threads share a row)
    int pr[KP];
    const int grow = tid >> 2;          // 0..63 : row within A tile
    const int gcs = (tid & 3) * 2;      // float4 index pair within 8-float4 chunk row
    if (MODE == 1) {
        const int4* ip = (const int4*)(idx + (size_t)(bm + grow) * KP);
        #pragma unroll
        for (int i = 0; i < 4; i++) {
            int4 v = ip[i];
            pr[i*4+0] = v.x; pr[i*4+1] = v.y; pr[i*4+2] = v.z; pr[i*4+3] = v.w;
        }
    }

    float4 pa[2];          // MODE0 A prefetch
    float4 s0, s1;         // MODE1 gather accumulators
    float4 pb[4];          // B prefetch

    auto prefetchA = [&](int kc) {
        if (MODE == 0) {
            #pragma unroll
            for (int i = 0; i < 2; i++) {
                int e = tid + i * 256, row = e >> 3, v = e & 7;
                pa[i] = A4[(size_t)(bm + row) * 64 + kc * 8 + v];
            }
        } else {
            s0 = make_float4(0.f, 0.f, 0.f, 0.f); s1 = s0;
            #pragma unroll
            for (int p = 0; p < KP; p++) {
                const float4* rp = A4 + (size_t)pr[p] * 64 + kc * 8 + gcs;
                float4 v0 = rp[0], v1 = rp[1];
                s0.x += v0.x; s0.y += v0.y; s0.z += v0.z; s0.w += v0.w;
                s1.x += v1.x; s1.y += v1.y; s1.z += v1.z; s1.w += v1.w;
            }
        }
    };
    auto prefetchB = [&](int kc) {
        #pragma unroll
        for (int i = 0; i < 4; i++) {
            int e = tid + i * 256, n = e >> 3, v = e & 7;
            pb[i] = B4[(size_t)(bn + n) * 64 + kc * 8 + v];
        }
    };
    auto stsAB = [&](int buf) {
        if (MODE == 0) {
            #pragma unroll
            for (int i = 0; i < 2; i++) {
                int e = tid + i * 256, row = e >> 3, v = e & 7;
                uint4 u = {f2tf(pa[i].x), f2tf(pa[i].y), f2tf(pa[i].z), f2tf(pa[i].w)};
                *(uint4*)(Asu + buf * A_FLOATS + row * PAD + v * 4) = u;
            }
        } else {
            const float inv = 1.0f / 16.0f;
            uint4 u0 = {f2tf(s0.x*inv), f2tf(s0.y*inv), f2tf(s0.z*inv), f2tf(s0.w*inv)};
            uint4 u1 = {f2tf(s1.x*inv), f2tf(s1.y*inv), f2tf(s1.z*inv), f2tf(s1.w*inv)};
            uint32_t* p = Asu + buf * A_FLOATS + grow * PAD + gcs * 4;
            *(uint4*)p = u0;
            *(uint4*)(p + 4) = u1;
        }
        #pragma unroll
        for (int i = 0; i < 4; i++) {
            int e = tid + i * 256, n = e >> 3, v = e & 7;
            uint4 u = {f2tf(pb[i].x), f2tf(pb[i].y), f2tf(pb[i].z), f2tf(pb[i].w)};
            *(uint4*)(Bsu + buf * B_FLOATS + n * PAD + v * 4) = u;
        }
    };

    float acc[2][4][4] = {};

    auto compute = [&](int buf) {
        const uint32_t* Ab = Asu + buf * A_FLOATS;
        const uint32_t* Bb = Bsu + buf * B_FLOATS;
        #pragma unroll
        for (int ks = 0; ks < 4; ks++) {
            const int k0 = ks * 8;
            uint32_t a[2][4], b[4][2];
            #pragma unroll
            for (int mf = 0; mf < 2; mf++) {
                const uint32_t* r0 = Ab + (wm + mf*16 + g) * PAD + k0 + t;
                const uint32_t* r1 = Ab + (wm + mf*16 + 8 + g) * PAD + k0 + t;
                a[mf][0] = r0[0]; a[mf][1] = r1[0]; a[mf][2] = r0[4]; a[mf][3] = r1[4];
            }
            #pragma unroll
            for (int nf = 0; nf < 4; nf++) {
                const uint32_t* rb = Bb + (wn + nf*8 + g) * PAD + k0 + t;
                b[nf][0] = rb[0]; b[nf][1] = rb[4];
            }
            #pragma unroll
            for (int mf = 0; mf < 2; mf++)
                #pragma unroll
                for (int nf = 0; nf < 4; nf++)
                    mma_tf32(acc[mf][nf], a[mf], b[nf]);
        }
    };

    // Software pipeline: reg-prefetch next chunk while computing current.
    prefetchA(0); prefetchB(0);
    stsAB(0);
    __syncthreads();
    #pragma unroll
    for (int kc = 0; kc < DD / BK; kc++) {
        if (kc < DD / BK - 1) { prefetchA(kc + 1); prefetchB(kc + 1); }
        compute(kc & 1);
        if (kc < DD / BK - 1) { stsAB((kc + 1) & 1); __syncthreads(); }
    }

    // Epilogue: bias + relu (+ residual)
    #pragma unroll
    for (int mf = 0; mf < 2; mf++) {
        const int r0 = bm + wm + mf*16 + g;
        #pragma unroll
        for (int nf = 0; nf < 4; nf++) {
            const int col = bn + wn + nf*8 + 2*t;
            float2 bb = *(const float2*)(bias + col);
            float2 v0, v1;
            v0.x = fmaxf(acc[mf][nf][0] + bb.x, 0.f);
            v0.y = fmaxf(acc[mf][nf][1] + bb.y, 0.f);
            v1.x = fmaxf(acc[mf][nf][2] + bb.x, 0.f);
            v1.y = fmaxf(acc[mf][nf][3] + bb.y, 0.f);
            if (ADD_RES) {
                float2 q0 = *(const float2*)(res + (size_t)r0 * DD + col);
                float2 q1 = *(const float2*)(res + (size_t)(r0 + 8) * DD + col);
                v0.x += q0.x; v0.y += q0.y; v1.x += q1.x; v1.y += q1.y;
            }
            *(float2*)(C + (size_t)r0 * DD + col) = v0;
            *(float2*)(C + (size_t)(r0 + 8) * DD + col) = v1;
        }
    }
}

// ---------------- 256x256 transpose (weights -> N-major B operand) ----------------
__global__ void transpose256(const float* __restrict__ W, float* __restrict__ Wt) {
    __shared__ float tbuf[32][33];
    const int bx = (blockIdx.x & 7) * 32;
    const int by = (blockIdx.x >> 3) * 32;
    const int x = threadIdx.x, y = threadIdx.y;
    #pragma unroll
    for (int i = 0; i < 32; i += 8)
        tbuf[y + i][x] = W[(by + y + i) * DD + bx + x];
    __syncthreads();
    #pragma unroll
    for (int i = 0; i < 32; i += 8)
        Wt[(bx + y + i) * DD + by + x] = tbuf[x][y + i];
}

// ---------------- Launch ----------------
extern "C" void kernel_launch(void* const* d_in, const int* in_sizes, int n_in,
                              void* d_out, int out_size)
{
    const float* x   = (const float*)d_in[0];   // [L, N, D]
    const int*   idx = (const int*)  d_in[1];   // [L-1, N, K]
    const float* W1  = (const float*)d_in[2];   // [D, D]
    const float* b1  = (const float*)d_in[3];   // [D]
    const float* W2  = (const float*)d_in[4];   // [D, D]
    const float* b2  = (const float*)d_in[5];   // [D]
    float* out = (float*)d_out;                 // [L, N, D]

    float *msgp, *w1t, *w2t;
    cudaGetSymbolAddress((void**)&msgp, g_msg);
    cudaGetSymbolAddress((void**)&w1t,  g_W1t);
    cudaGetSymbolAddress((void**)&w2t,  g_W2t);

    cudaFuncSetAttribute(gemm_mma<0, false>, cudaFuncAttributeMaxDynamicSharedMemorySize, SMEM_BYTES);
    cudaFuncSetAttribute(gemm_mma<1, true>,  cudaFuncAttributeMaxDynamicSharedMemorySize, SMEM_BYTES);

    const size_t lvl = (size_t)NN * DD;

    // Pre-transpose weights (B operand is col-major [n][k] for mma row.col)
    transpose256<<<64, dim3(32, 8)>>>(W1, w1t);
    transpose256<<<64, dim3(32, 8)>>>(W2, w2t);

    // Level 0: passthrough
    cudaMemcpyAsync(out, x, lvl * sizeof(float), cudaMemcpyDeviceToDevice);

    const dim3 grid(DD / BN, NN / BM);   // (2, 256)

    for (int l = 1; l < LL; l++) {
        const float* yprev = out + (size_t)(l - 1) * lvl;
        // msg = relu(yprev @ W1 + b1)
        gemm_mma<0, false><<<grid, 256, SMEM_BYTES>>>(yprev, nullptr, w1t, b1, nullptr, msgp);
        // y = relu(mean_p msg[idx] @ W2 + b2) + x[l]   (gather fused into A-load)
        gemm_mma<1, true><<<grid, 256, SMEM_BYTES>>>(msgp, idx + (size_t)(l - 1) * NN * KP,
                                                     w2t, b2, x + (size_t)l * lvl,
                                                     out + (size_t)l * lvl);
    }
}

// round 7
// speedup vs baseline: 1.3881x; 1.3862x over previous
#include <cuda_runtime.h>
#include <cstdint>

// ---------------- Problem constants ----------------
constexpr int NN = 16384;   // nodes per level
constexpr int DD = 256;     // feature dim
constexpr int KP = 16;      // in-degree
constexpr int LL = 16;      // levels

// ---------------- GEMM tiling ----------------
constexpr int BM = 64, BN = 128, BK = 32;
constexpr int PAD = 36;                    // SMEM row stride in floats (16B-aligned, conflict-free)
constexpr int A_FLOATS = BM * PAD;         // 2304
constexpr int B_FLOATS = BN * PAD;         // 4608
constexpr int SMEM_BYTES = 2 * (A_FLOATS + B_FLOATS) * 4;  // 55296

// ---------------- Scratch (__device__ globals; alloc-free rule) ----------------
__device__ float g_msg[NN * DD];
__device__ float g_H[NN * DD];
__device__ float g_W1t[DD * DD];   // W1^T : Wt[n][k] = W[k][n]
__device__ float g_W2t[DD * DD];

// ---------------- Portable PTX helpers (no 'a'-suffix features) ----------------
__device__ __forceinline__ uint32_t smem_u32(const void* p) {
    uint32_t a;
    asm("{ .reg .u64 t; cvta.to.shared.u64 t, %1; cvt.u32.u64 %0, t; }" : "=r"(a) : "l"(p));
    return a;
}
__device__ __forceinline__ void cp16(uint32_t dst, const void* src) {
    asm volatile("cp.async.cg.shared.global [%0], [%1], 16;" :: "r"(dst), "l"(src));
}
#define CP_COMMIT() asm volatile("cp.async.commit_group;" ::: "memory")
#define CP_WAIT(n)  asm volatile("cp.async.wait_group %0;" :: "n"(n) : "memory")

__device__ __forceinline__ void mma_tf32(float* c, const uint32_t* a, const uint32_t* b) {
    asm volatile("mma.sync.aligned.m16n8k8.row.col.f32.tf32.tf32.f32 "
                 "{%0,%1,%2,%3}, {%4,%5,%6,%7}, {%8,%9}, {%0,%1,%2,%3};"
                 : "+f"(c[0]), "+f"(c[1]), "+f"(c[2]), "+f"(c[3])
                 : "r"(a[0]), "r"(a[1]), "r"(a[2]), "r"(a[3]), "r"(b[0]), "r"(b[1]));
}

// ---------------- Streaming tf32 GEMM:  C = [relu](A @ Bt^T [+ bias]) ----------------
// A [NN, 256] f32 row-major; Bt [256 n][256 k] (pre-transposed weights).
// Block: 256 threads = 8 warps (2m x 4n), warp tile 32x32, K in 8 chunks of 32.
// Operands staged GMEM->SMEM with cp.async (raw f32 bits -> tf32 MMA, truncating).
template<bool BIAS_RELU>
__global__ __launch_bounds__(256) void gemm_tf32(
    const float* __restrict__ A, const float* __restrict__ Bt,
    const float* __restrict__ bias, float* __restrict__ C)
{
    extern __shared__ float sm[];
    uint32_t* Asu = (uint32_t*)sm;                    // [2][BM][PAD]
    uint32_t* Bsu = (uint32_t*)(sm + 2 * A_FLOATS);   // [2][BN][PAD]
    const uint32_t As_addr = smem_u32(Asu);
    const uint32_t Bs_addr = smem_u32(Bsu);

    const int tid = threadIdx.x;
    const int lane = tid & 31, wid = tid >> 5;
    const int g = lane >> 2, t = lane & 3;
    const int wm = (wid & 1) * 32, wn = (wid >> 1) * 32;
    const int bm = blockIdx.y * BM, bn = blockIdx.x * BN;

    // load mappings (one 16B cp.async per element)
    const int ar = tid >> 3, av = tid & 7;            // A: rows ar, ar+32 ; col float4 av
    const int br = tid >> 3, bv = tid & 7;            // B: rows br, +32, +64, +96

    auto issue = [&](int kc, int buf) {
        const float* Ab = A + (size_t)(bm + ar) * DD + kc * BK + av * 4;
        uint32_t ad = As_addr + (uint32_t)(buf * A_FLOATS + ar * PAD + av * 4) * 4;
        cp16(ad, Ab);
        cp16(ad + 32u * PAD * 4u, Ab + (size_t)32 * DD);
        const float* Bb = Bt + (size_t)(bn + br) * DD + kc * BK + bv * 4;
        uint32_t bd = Bs_addr + (uint32_t)(buf * B_FLOATS + br * PAD + bv * 4) * 4;
        #pragma unroll
        for (int i = 0; i < 4; i++)
            cp16(bd + (uint32_t)(i * 32 * PAD) * 4u, Bb + (size_t)(i * 32) * DD);
        CP_COMMIT();
    };

    float acc[2][4][4] = {};

    auto compute = [&](int buf) {
        const uint32_t* Ab = Asu + buf * A_FLOATS;
        const uint32_t* Bb = Bsu + buf * B_FLOATS;
        #pragma unroll
        for (int ks = 0; ks < 4; ks++) {
            const int k0 = ks * 8;
            uint32_t a[2][4], b[4][2];
            #pragma unroll
            for (int mf = 0; mf < 2; mf++) {
                const uint32_t* r0 = Ab + (wm + mf*16 + g) * PAD + k0 + t;
                const uint32_t* r1 = Ab + (wm + mf*16 + 8 + g) * PAD + k0 + t;
                a[mf][0] = r0[0]; a[mf][1] = r1[0]; a[mf][2] = r0[4]; a[mf][3] = r1[4];
            }
            #pragma unroll
            for (int nf = 0; nf < 4; nf++) {
                const uint32_t* rb = Bb + (wn + nf*8 + g) * PAD + k0 + t;
                b[nf][0] = rb[0]; b[nf][1] = rb[4];
            }
            #pragma unroll
            for (int mf = 0; mf < 2; mf++)
                #pragma unroll
                for (int nf = 0; nf < 4; nf++)
                    mma_tf32(acc[mf][nf], a[mf], b[nf]);
        }
    };

    issue(0, 0);
    #pragma unroll
    for (int kc = 0; kc < DD / BK; kc++) {
        if (kc + 1 < DD / BK) {
            issue(kc + 1, (kc + 1) & 1);
            CP_WAIT(1);
        } else {
            CP_WAIT(0);
        }
        __syncthreads();
        compute(kc & 1);
        __syncthreads();
    }

    // Epilogue
    #pragma unroll
    for (int mf = 0; mf < 2; mf++) {
        const int r0 = bm + wm + mf*16 + g;
        #pragma unroll
        for (int nf = 0; nf < 4; nf++) {
            const int col = bn + wn + nf*8 + 2*t;
            float2 v0, v1;
            if (BIAS_RELU) {
                float2 bb = *(const float2*)(bias + col);
                v0.x = fmaxf(acc[mf][nf][0] + bb.x, 0.f);
                v0.y = fmaxf(acc[mf][nf][1] + bb.y, 0.f);
                v1.x = fmaxf(acc[mf][nf][2] + bb.x, 0.f);
                v1.y = fmaxf(acc[mf][nf][3] + bb.y, 0.f);
            } else {
                v0.x = acc[mf][nf][0]; v0.y = acc[mf][nf][1];
                v1.x = acc[mf][nf][2]; v1.y = acc[mf][nf][3];
            }
            *(float2*)(C + (size_t)r0 * DD + col) = v0;
            *(float2*)(C + (size_t)(r0 + 8) * DD + col) = v1;
        }
    }
}

// ---------------- Gather epilogue:  y = relu(mean_p H[idx_p] + b2) + x ----------------
// 4 nodes per 256-thread block; 64 threads per node, one float4 column chunk each.
__global__ __launch_bounds__(256) void gather_epi(
    const float* __restrict__ H, const int* __restrict__ idx,
    const float* __restrict__ b2, const float* __restrict__ x,
    float* __restrict__ y)
{
    const int node = blockIdx.x * 4 + (threadIdx.x >> 6);
    const int c = (threadIdx.x & 63) * 4;
    const int4* ip = (const int4*)(idx + (size_t)node * KP);

    int pr[KP];
    #pragma unroll
    for (int i = 0; i < 4; i++) {
        int4 v = ip[i];
        pr[i*4+0] = v.x; pr[i*4+1] = v.y; pr[i*4+2] = v.z; pr[i*4+3] = v.w;
    }

    float4 s = {0.f, 0.f, 0.f, 0.f};
    #pragma unroll
    for (int p = 0; p < KP; p++) {
        float4 v = *(const float4*)(H + (size_t)pr[p] * DD + c);
        s.x += v.x; s.y += v.y; s.z += v.z; s.w += v.w;
    }
    const float inv = 1.0f / (float)KP;
    float4 bb = *(const float4*)(b2 + c);
    float4 xx = *(const float4*)(x + (size_t)node * DD + c);
    float4 o;
    o.x = fmaxf(s.x * inv + bb.x, 0.f) + xx.x;
    o.y = fmaxf(s.y * inv + bb.y, 0.f) + xx.y;
    o.z = fmaxf(s.z * inv + bb.z, 0.f) + xx.z;
    o.w = fmaxf(s.w * inv + bb.w, 0.f) + xx.w;
    *(float4*)(y + (size_t)node * DD + c) = o;
}

// ---------------- 256x256 transpose (weights -> N-major B operand) ----------------
__global__ void transpose256(const float* __restrict__ W, float* __restrict__ Wt) {
    __shared__ float tbuf[32][33];
    const int bx = (blockIdx.x & 7) * 32;
    const int by = (blockIdx.x >> 3) * 32;
    const int x = threadIdx.x, y = threadIdx.y;
    #pragma unroll
    for (int i = 0; i < 32; i += 8)
        tbuf[y + i][x] = W[(by + y + i) * DD + bx + x];
    __syncthreads();
    #pragma unroll
    for (int i = 0; i < 32; i += 8)
        Wt[(bx + y + i) * DD + by + x] = tbuf[x][y + i];
}

// ---------------- Launch ----------------
extern "C" void kernel_launch(void* const* d_in, const int* in_sizes, int n_in,
                              void* d_out, int out_size)
{
    const float* x   = (const float*)d_in[0];   // [L, N, D]
    const int*   idx = (const int*)  d_in[1];   // [L-1, N, K]
    const float* W1  = (const float*)d_in[2];   // [D, D]
    const float* b1  = (const float*)d_in[3];   // [D]
    const float* W2  = (const float*)d_in[4];   // [D, D]
    const float* b2  = (const float*)d_in[5];   // [D]
    float* out = (float*)d_out;                 // [L, N, D]

    float *msgp, *Hp, *w1t, *w2t;
    cudaGetSymbolAddress((void**)&msgp, g_msg);
    cudaGetSymbolAddress((void**)&Hp,   g_H);
    cudaGetSymbolAddress((void**)&w1t,  g_W1t);
    cudaGetSymbolAddress((void**)&w2t,  g_W2t);

    cudaFuncSetAttribute(gemm_tf32<true>,  cudaFuncAttributeMaxDynamicSharedMemorySize, SMEM_BYTES);
    cudaFuncSetAttribute(gemm_tf32<false>, cudaFuncAttributeMaxDynamicSharedMemorySize, SMEM_BYTES);

    const size_t lvl = (size_t)NN * DD;

    transpose256<<<64, dim3(32, 8)>>>(W1, w1t);
    transpose256<<<64, dim3(32, 8)>>>(W2, w2t);

    // Level 0: passthrough
    cudaMemcpyAsync(out, x, lvl * sizeof(float), cudaMemcpyDeviceToDevice);

    const dim3 grid(DD / BN, NN / BM);   // (2, 256)

    for (int l = 1; l < LL; l++) {
        const float* yprev = out + (size_t)(l - 1) * lvl;
        // msg = relu(yprev @ W1 + b1)
        gemm_tf32<true><<<grid, 256, SMEM_BYTES>>>(yprev, w1t, b1, msgp);
        // H = msg @ W2   (bias/relu deferred to gather stage; mean commutes with linear map)
        gemm_tf32<false><<<grid, 256, SMEM_BYTES>>>(msgp, w2t, nullptr, Hp);
        // y = relu(mean_p H[idx_p] + b2) + x[l]
        gather_epi<<<NN / 4, 256>>>(Hp, idx + (size_t)(l - 1) * NN * KP, b2,
                                    x + (size_t)l * lvl, out + (size_t)l * lvl);
    }
}

// round 8
// speedup vs baseline: 1.5243x; 1.0981x over previous
#include <cuda_runtime.h>
#include <cstdint>

// ---------------- Problem constants ----------------
constexpr int NN = 16384;   // nodes per level
constexpr int DD = 256;     // feature dim
constexpr int KP = 16;      // in-degree
constexpr int LL = 16;      // levels

// ---------------- GEMM tiling ----------------
constexpr int BM = 128, BN = 128, BK = 32;
constexpr int STAGES = 3;
constexpr int PAD = 36;                         // floats per SMEM row (conflict-free)
constexpr int A_FLOATS = BM * PAD;              // 4608
constexpr int B_FLOATS = BN * PAD;              // 4608
constexpr int STAGE_BYTES = (A_FLOATS + B_FLOATS) * 4;       // 36864
constexpr int SMEM_BYTES = STAGES * STAGE_BYTES;             // 110592

// ---------------- Scratch (__device__ globals; alloc-free rule) ----------------
__device__ float g_msg[NN * DD];
__device__ float g_H[NN * DD];
__device__ float g_W1t[DD * DD];   // W1^T, tf32-rna rounded
__device__ float g_W2t[DD * DD];   // W2^T, tf32-rna rounded

// ---------------- Portable PTX helpers (no 'a'-suffix features) ----------------
__device__ __forceinline__ uint32_t smem_u32(const void* p) {
    uint32_t a;
    asm("{ .reg .u64 t; cvta.to.shared.u64 t, %1; cvt.u32.u64 %0, t; }" : "=r"(a) : "l"(p));
    return a;
}
__device__ __forceinline__ void cp16(uint32_t dst, const void* src) {
    asm volatile("cp.async.cg.shared.global [%0], [%1], 16;" :: "r"(dst), "l"(src));
}
#define CP_COMMIT() asm volatile("cp.async.commit_group;" ::: "memory")
#define CP_WAIT(n)  asm volatile("cp.async.wait_group %0;" :: "n"(n) : "memory")

__device__ __forceinline__ void ldsm4(uint32_t& r0, uint32_t& r1, uint32_t& r2, uint32_t& r3,
                                      uint32_t addr) {
    asm volatile("ldmatrix.sync.aligned.m8n8.x4.shared.b16 {%0,%1,%2,%3}, [%4];"
                 : "=r"(r0), "=r"(r1), "=r"(r2), "=r"(r3) : "r"(addr));
}
__device__ __forceinline__ void mma_tf32(float* c, uint32_t a0, uint32_t a1, uint32_t a2,
                                         uint32_t a3, uint32_t b0, uint32_t b1) {
    asm volatile("mma.sync.aligned.m16n8k8.row.col.f32.tf32.tf32.f32 "
                 "{%0,%1,%2,%3}, {%4,%5,%6,%7}, {%8,%9}, {%0,%1,%2,%3};"
                 : "+f"(c[0]), "+f"(c[1]), "+f"(c[2]), "+f"(c[3])
                 : "r"(a0), "r"(a1), "r"(a2), "r"(a3), "r"(b0), "r"(b1));
}

// ---------------- Streaming tf32 GEMM:  C = [relu](A @ Bt^T [+ bias]) ----------------
// A [NN,256] f32 row-major; Bt [256 n][256 k] pre-transposed + tf32-rna rounded.
// 256 threads = 8 warps (2m x 4n), warp tile 64x32, BM=BN=128, K in 8 chunks of 32.
// cp.async 3-stage pipeline; ldmatrix fragment loads; f32 bits fed to tf32 MMA.
template<bool BIAS_RELU>
__global__ __launch_bounds__(256, 2) void gemm_tf32(
    const float* __restrict__ A, const float* __restrict__ Bt,
    const float* __restrict__ bias, float* __restrict__ C)
{
    extern __shared__ float sm[];
    const uint32_t smb = smem_u32(sm);

    const int tid = threadIdx.x;
    const int lane = tid & 31, wid = tid >> 5;
    const int g = lane >> 2, t = lane & 3;
    const int wm = (wid & 1) * 64;          // 2 m-warps * 64
    const int wn = (wid >> 1) * 32;         // 4 n-warps * 32
    const int bm = blockIdx.y * BM, bn = blockIdx.x * BN;

    // ---- cp.async load mapping: 4 A-blocks + 4 B-blocks of 16B per thread ----
    const float* Ag[4]; const float* Bg[4];
    uint32_t Asm[4], Bsm[4];
    #pragma unroll
    for (int i = 0; i < 4; i++) {
        int e = tid + i * 256;              // 0..1023
        int row = e >> 3, v = e & 7;
        Ag[i] = A  + (size_t)(bm + row) * DD + v * 4;
        Bg[i] = Bt + (size_t)(bn + row) * DD + v * 4;
        Asm[i] = smb + (uint32_t)(row * PAD + v * 4) * 4u;
        Bsm[i] = smb + (uint32_t)(A_FLOATS + row * PAD + v * 4) * 4u;
    }

    auto issue = [&](int kc, int stage) {
        const uint32_t so = (uint32_t)stage * STAGE_BYTES;
        const int go = kc * BK;
        #pragma unroll
        for (int i = 0; i < 4; i++) cp16(Asm[i] + so, Ag[i] + go);
        #pragma unroll
        for (int i = 0; i < 4; i++) cp16(Bsm[i] + so, Bg[i] + go);
        CP_COMMIT();
    };

    // ---- ldmatrix base addresses ----
    const int lr = (lane & 7) + ((lane & 16) >> 1);   // 0..15 row within frag group
    const int lc = (lane & 8) >> 1;                   // 0 or 4 col
    uint32_t a_base[4], b_base[2];
    #pragma unroll
    for (int mf = 0; mf < 4; mf++)
        a_base[mf] = smb + (uint32_t)((wm + mf * 16 + lr) * PAD + lc) * 4u;
    #pragma unroll
    for (int np = 0; np < 2; np++)
        b_base[np] = smb + (uint32_t)(A_FLOATS + (wn + np * 16 + lr) * PAD + lc) * 4u;

    float acc[4][4][4] = {};

    auto compute = [&](int stage) {
        const uint32_t so = (uint32_t)stage * STAGE_BYTES;
        #pragma unroll
        for (int ks = 0; ks < 4; ks++) {
            const uint32_t ko = so + ks * 32u;
            uint32_t a[4][4], b[2][4];
            #pragma unroll
            for (int mf = 0; mf < 4; mf++)
                ldsm4(a[mf][0], a[mf][1], a[mf][2], a[mf][3], a_base[mf] + ko);
            #pragma unroll
            for (int np = 0; np < 2; np++)
                ldsm4(b[np][0], b[np][1], b[np][2], b[np][3], b_base[np] + ko);
            #pragma unroll
            for (int mf = 0; mf < 4; mf++)
                #pragma unroll
                for (int nf = 0; nf < 4; nf++)
                    mma_tf32(acc[mf][nf],
                             a[mf][0], a[mf][2], a[mf][1], a[mf][3],   // {a0,a1,a2,a3}
                             b[nf >> 1][(nf & 1) * 2], b[nf >> 1][(nf & 1) * 2 + 1]);
        }
    };

    // ---- pipeline: 3 stages, one sync per chunk ----
    issue(0, 0);
    issue(1, 1);
    #pragma unroll
    for (int kc = 0; kc < DD / BK; kc++) {
        CP_WAIT(1);
        __syncthreads();
        if (kc + 2 < DD / BK) issue(kc + 2, (kc + 2) % STAGES);
        compute(kc % STAGES);
    }

    // ---- epilogue ----
    #pragma unroll
    for (int mf = 0; mf < 4; mf++) {
        const int r0 = bm + wm + mf * 16 + g;
        #pragma unroll
        for (int nf = 0; nf < 4; nf++) {
            const int col = bn + wn + nf * 8 + 2 * t;
            float2 v0, v1;
            if (BIAS_RELU) {
                float2 bb = *(const float2*)(bias + col);
                v0.x = fmaxf(acc[mf][nf][0] + bb.x, 0.f);
                v0.y = fmaxf(acc[mf][nf][1] + bb.y, 0.f);
                v1.x = fmaxf(acc[mf][nf][2] + bb.x, 0.f);
                v1.y = fmaxf(acc[mf][nf][3] + bb.y, 0.f);
            } else {
                v0.x = acc[mf][nf][0]; v0.y = acc[mf][nf][1];
                v1.x = acc[mf][nf][2]; v1.y = acc[mf][nf][3];
            }
            *(float2*)(C + (size_t)r0 * DD + col) = v0;
            *(float2*)(C + (size_t)(r0 + 8) * DD + col) = v1;
        }
    }
}

// ---------------- Gather epilogue:  y = relu(mean_p H[idx_p] + b2) + x ----------------
__global__ __launch_bounds__(256) void gather_epi(
    const float* __restrict__ H, const int* __restrict__ idx,
    const float* __restrict__ b2, const float* __restrict__ x,
    float* __restrict__ y)
{
    const int node = blockIdx.x * 4 + (threadIdx.x >> 6);
    const int c = (threadIdx.x & 63) * 4;
    const int4* ip = (const int4*)(idx + (size_t)node * KP);

    int pr[KP];
    #pragma unroll
    for (int i = 0; i < 4; i++) {
        int4 v = ip[i];
        pr[i*4+0] = v.x; pr[i*4+1] = v.y; pr[i*4+2] = v.z; pr[i*4+3] = v.w;
    }

    float4 s = {0.f, 0.f, 0.f, 0.f};
    #pragma unroll
    for (int p = 0; p < KP; p++) {
        float4 v = *(const float4*)(H + (size_t)pr[p] * DD + c);
        s.x += v.x; s.y += v.y; s.z += v.z; s.w += v.w;
    }
    const float inv = 1.0f / (float)KP;
    float4 bb = *(const float4*)(b2 + c);
    float4 xx = *(const float4*)(x + (size_t)node * DD + c);
    float4 o;
    o.x = fmaxf(s.x * inv + bb.x, 0.f) + xx.x;
    o.y = fmaxf(s.y * inv + bb.y, 0.f) + xx.y;
    o.z = fmaxf(s.z * inv + bb.z, 0.f) + xx.z;
    o.w = fmaxf(s.w * inv + bb.w, 0.f) + xx.w;
    *(float4*)(y + (size_t)node * DD + c) = o;
}

// ------- 256x256 transpose + tf32-rna round (weights -> N-major B operand) -------
__global__ void transpose256(const float* __restrict__ W, float* __restrict__ Wt) {
    __shared__ float tbuf[32][33];
    const int bx = (blockIdx.x & 7) * 32;
    const int by = (blockIdx.x >> 3) * 32;
    const int x = threadIdx.x, y = threadIdx.y;
    #pragma unroll
    for (int i = 0; i < 32; i += 8)
        tbuf[y + i][x] = W[(by + y + i) * DD + bx + x];
    __syncthreads();
    #pragma unroll
    for (int i = 0; i < 32; i += 8) {
        uint32_t r;
        asm("cvt.rna.tf32.f32 %0, %1;" : "=r"(r) : "f"(tbuf[x][y + i]));
        Wt[(bx + y + i) * DD + by + x] = __uint_as_float(r);
    }
}

// ---------------- Launch ----------------
extern "C" void kernel_launch(void* const* d_in, const int* in_sizes, int n_in,
                              void* d_out, int out_size)
{
    const float* x   = (const float*)d_in[0];   // [L, N, D]
    const int*   idx = (const int*)  d_in[1];   // [L-1, N, K]
    const float* W1  = (const float*)d_in[2];   // [D, D]
    const float* b1  = (const float*)d_in[3];   // [D]
    const float* W2  = (const float*)d_in[4];   // [D, D]
    const float* b2  = (const float*)d_in[5];   // [D]
    float* out = (float*)d_out;                 // [L, N, D]

    float *msgp, *Hp, *w1t, *w2t;
    cudaGetSymbolAddress((void**)&msgp, g_msg);
    cudaGetSymbolAddress((void**)&Hp,   g_H);
    cudaGetSymbolAddress((void**)&w1t,  g_W1t);
    cudaGetSymbolAddress((void**)&w2t,  g_W2t);

    cudaFuncSetAttribute(gemm_tf32<true>,  cudaFuncAttributeMaxDynamicSharedMemorySize, SMEM_BYTES);
    cudaFuncSetAttribute(gemm_tf32<false>, cudaFuncAttributeMaxDynamicSharedMemorySize, SMEM_BYTES);

    const size_t lvl = (size_t)NN * DD;

    transpose256<<<64, dim3(32, 8)>>>(W1, w1t);
    transpose256<<<64, dim3(32, 8)>>>(W2, w2t);

    // Level 0: passthrough
    cudaMemcpyAsync(out, x, lvl * sizeof(float), cudaMemcpyDeviceToDevice);

    const dim3 grid(DD / BN, NN / BM);   // (2, 128) = 256 CTAs, all resident at occ 2

    for (int l = 1; l < LL; l++) {
        const float* yprev = out + (size_t)(l - 1) * lvl;
        // msg = relu(yprev @ W1 + b1)
        gemm_tf32<true><<<grid, 256, SMEM_BYTES>>>(yprev, w1t, b1, msgp);
        // H = msg @ W2   (bias/relu deferred; mean commutes with the linear map)
        gemm_tf32<false><<<grid, 256, SMEM_BYTES>>>(msgp, w2t, nullptr, Hp);
        // y = relu(mean_p H[idx_p] + b2) + x[l]
        gather_epi<<<NN / 4, 256>>>(Hp, idx + (size_t)(l - 1) * NN * KP, b2,
                                    x + (size_t)l * lvl, out + (size_t)l * lvl);
    }
}